// round 11
// baseline (speedup 1.0000x reference)
#include <cuda_runtime.h>
#include <math.h>

// Problem constants
static const int Bc  = 128;    // batch
static const int Tc  = 256;    // time steps
static const int Rc  = 1024;   // recurrent width

// ---------------------------------------------------------------------------
// Device scratch (no allocations allowed -> __device__ globals)
// ---------------------------------------------------------------------------
__device__ float g_x [32768 * 256];      // gathered embeddings, row = t*B + b
__device__ float g_xh[33554432];         // xh[t*B+b][r]  (x@Wh0x + bh0)
__device__ float g_xt[33554432];         // xt[t*B+b][r]  (x@Wt0x + bt0)
__device__ float g_s [2][128 * 1024];    // ping-pong state, row-major [b][r]
__device__ unsigned g_cnt = 0;           // grid barrier arrival counter
__device__ unsigned g_gen = 0;           // grid barrier generation

// 4-wide multiply-accumulate (function, NOT a macro: a macro parameter named
// `w` would capture the `.w` member token and break expansion).
static __device__ __forceinline__ void acc4(float& acc, const float4& a,
                                            const float4& b) {
    acc += a.x * b.x;
    acc += a.y * b.y;
    acc += a.z * b.z;
    acc += a.w * b.w;
}

// Component-wise FMA into a float4 accumulator: 4 independent chains.
static __device__ __forceinline__ void acc4v(float4& acc, const float4& a,
                                             const float4& b) {
    acc.x += a.x * b.x;
    acc.y += a.y * b.y;
    acc.z += a.z * b.z;
    acc.w += a.w * b.w;
}

static __device__ __forceinline__ float hsum(const float4& v) {
    return (v.x + v.y) + (v.z + v.w);
}

// Software grid barrier for a co-resident 128-CTA persistent kernel.
static __device__ __forceinline__ void gbar() {
    __threadfence();
    __syncthreads();
    if (threadIdx.x == 0) {
        unsigned g = *((volatile unsigned*)&g_gen);
        if (atomicAdd(&g_cnt, 1) == gridDim.x - 1) {
            g_cnt = 0;
            __threadfence();
            atomicAdd(&g_gen, 1);
        } else {
            while (*((volatile unsigned*)&g_gen) == g) { }
        }
    }
    __syncthreads();
    __threadfence();
}

// ---------------------------------------------------------------------------
// Zero the initial state
// ---------------------------------------------------------------------------
__global__ void zero_kernel() {
    int i = blockIdx.x * 256 + threadIdx.x;          // 32768 float4
    ((float4*)g_s[0])[i] = make_float4(0.f, 0.f, 0.f, 0.f);
}

// ---------------------------------------------------------------------------
// Embedding gather: g_x[t*B+b][0:256] = emb[ids[b*T+t]][0:256]
// ---------------------------------------------------------------------------
__global__ void gather_kernel(const int* __restrict__ ids,
                              const float* __restrict__ emb) {
    int idx = blockIdx.x * 256 + threadIdx.x;        // 32768 rows * 64 f4
    int row = idx >> 6;
    int c   = (idx & 63) << 2;
    int t = row >> 7;            // B = 128
    int b = row & 127;
    int id = ids[b * Tc + t];
    *(float4*)&g_x[(size_t)row * 256 + c] =
        *(const float4*)&emb[(size_t)id * 256 + c];
}

// ---------------------------------------------------------------------------
// Prologue dual GEMM: xh = x@Whx + bh ; xt = x@Wtx + bt  (unchanged)
// ---------------------------------------------------------------------------
__global__ __launch_bounds__(256) void prologue_kernel(
    const float* __restrict__ Whx, const float* __restrict__ Wtx,
    const float* __restrict__ bh,  const float* __restrict__ bt) {
    __shared__ float sA [2][64 * 36];
    __shared__ float sWh[2][16 * 36];
    __shared__ float sWt[2][16 * 36];

    const int tid = threadIdx.x;
    const int tx  = tid & 7;          // colgroup 0..7
    const int ty  = tid >> 3;         // rowgroup 0..31
    const int n0  = blockIdx.x * 16;
    const int m0  = blockIdx.y * 64;
    const int LDA = 256, LDW = 1024;

    const int sm  = tid >> 3;               // 0..31
    const int sk4 = (tid & 7) * 4;          // 0,4,...,28
    const int wn  = tid & 15;               // 0..15
    const int wk  = tid >> 4;               // 0..15

    float aH[2][2] = {{0.f,0.f},{0.f,0.f}};
    float aT[2][2] = {{0.f,0.f},{0.f,0.f}};

    #pragma unroll
    for (int r = 0; r < 2; r++) {
        int m = sm + r * 32;
        *(float4*)&sA[0][m * 36 + sk4] =
            *(const float4*)&g_x[(size_t)(m0 + m) * LDA + sk4];
    }
    #pragma unroll
    for (int r = 0; r < 2; r++) {
        int kk = wk + r * 16;
        sWh[0][wn * 36 + kk] = Whx[(size_t)kk * LDW + n0 + wn];
        sWt[0][wn * 36 + kk] = Wtx[(size_t)kk * LDW + n0 + wn];
    }
    __syncthreads();

    const int NS = 256 / 32;     // 8 stages
    for (int st = 0; st < NS; st++) {
        const int cur = st & 1;
        float4 pA0, pA1; float pWh0, pWh1, pWt0, pWt1;
        if (st + 1 < NS) {
            int k0 = (st + 1) * 32;
            pA0 = *(const float4*)&g_x[(size_t)(m0 + sm     ) * LDA + k0 + sk4];
            pA1 = *(const float4*)&g_x[(size_t)(m0 + sm + 32) * LDA + k0 + sk4];
            pWh0 = Whx[(size_t)(k0 + wk     ) * LDW + n0 + wn];
            pWh1 = Whx[(size_t)(k0 + wk + 16) * LDW + n0 + wn];
            pWt0 = Wtx[(size_t)(k0 + wk     ) * LDW + n0 + wn];
            pWt1 = Wtx[(size_t)(k0 + wk + 16) * LDW + n0 + wn];
        }
        #pragma unroll
        for (int k4 = 0; k4 < 8; k4++) {
            float4 a0 = *(const float4*)&sA [cur][ ty       * 36 + k4 * 4];
            float4 a1 = *(const float4*)&sA [cur][(ty + 32) * 36 + k4 * 4];
            float4 h0 = *(const float4*)&sWh[cur][ tx       * 36 + k4 * 4];
            float4 h1 = *(const float4*)&sWh[cur][(tx + 8 ) * 36 + k4 * 4];
            float4 q0 = *(const float4*)&sWt[cur][ tx       * 36 + k4 * 4];
            float4 q1 = *(const float4*)&sWt[cur][(tx + 8 ) * 36 + k4 * 4];
            acc4(aH[0][0], a0, h0); acc4(aH[0][1], a0, h1);
            acc4(aH[1][0], a1, h0); acc4(aH[1][1], a1, h1);
            acc4(aT[0][0], a0, q0); acc4(aT[0][1], a0, q1);
            acc4(aT[1][0], a1, q0); acc4(aT[1][1], a1, q1);
        }
        if (st + 1 < NS) {
            int nb = cur ^ 1;
            *(float4*)&sA[nb][ sm       * 36 + sk4] = pA0;
            *(float4*)&sA[nb][(sm + 32) * 36 + sk4] = pA1;
            sWh[nb][wn * 36 + wk     ] = pWh0;
            sWh[nb][wn * 36 + wk + 16] = pWh1;
            sWt[nb][wn * 36 + wk     ] = pWt0;
            sWt[nb][wn * 36 + wk + 16] = pWt1;
        }
        __syncthreads();
    }

    #pragma unroll
    for (int r = 0; r < 2; r++)
        #pragma unroll
        for (int c = 0; c < 2; c++) {
            int m = m0 + ty + r * 32;
            int n = n0 + tx + c * 8;
            g_xh[(size_t)m * 1024 + n] = aH[r][c] + bh[n];
            g_xt[(size_t)m * 1024 + n] = aT[r][c] + bt[n];
        }
}

// ---------------------------------------------------------------------------
// One highway phase (512-thread version):
//   h = tanh(addH + s@Wh);  g = sigmoid(addT + s@Wt);  s' = (h - s)*g + s
// CTA tile [64m x 16n x 2 gates]; this CTA: n0 = (bid&63)*16, m0 = (bid>>6)*64.
// 512 threads -> 16 warps/SM (4 per SMSP). Each thread: 4 outputs
// (m=ty, n in {tx, tx+8}, both gates), float4 component accumulators.
// State loads use __ldcg (L1-bypass) for cross-CTA coherence.
// ---------------------------------------------------------------------------
static __device__ void phase_step(
    const float* __restrict__ A, float* __restrict__ dst,
    const float* __restrict__ Wh, const float* __restrict__ Wt,
    const float* __restrict__ addH, const float* __restrict__ addT, int l0,
    float* sA, float* sWh, float* sWt)
{
    const int tid = threadIdx.x;
    const int tx  = tid & 7;           // n-col group
    const int ty  = tid >> 3;          // m-row 0..63
    const int n0  = (blockIdx.x & 63) * 16;
    const int m0  = (blockIdx.x >> 6) * 64;

    const int sm  = tid >> 3;          // staging row 0..63
    const int sk4 = (tid & 7) * 4;     // staging k-offset
    const int wn  = tid & 15;          // weight n 0..15
    const int wk  = tid >> 4;          // weight k 0..31

    float4 cH0 = make_float4(0.f,0.f,0.f,0.f);
    float4 cH1 = make_float4(0.f,0.f,0.f,0.f);
    float4 cT0 = make_float4(0.f,0.f,0.f,0.f);
    float4 cT1 = make_float4(0.f,0.f,0.f,0.f);

    // stage 0
    *(float4*)&sA[sm * 36 + sk4] =
        __ldcg((const float4*)&A[(size_t)(m0 + sm) * 1024 + sk4]);
    sWh[wn * 36 + wk] = Wh[(size_t)wk * 1024 + n0 + wn];
    sWt[wn * 36 + wk] = Wt[(size_t)wk * 1024 + n0 + wn];
    __syncthreads();

    for (int st = 0; st < 32; st++) {
        const int cur = st & 1;
        float4 pA; float pWh, pWt;
        if (st < 31) {
            int k0 = (st + 1) * 32;
            pA  = __ldcg((const float4*)&A[(size_t)(m0 + sm) * 1024 + k0 + sk4]);
            pWh = Wh[(size_t)(k0 + wk) * 1024 + n0 + wn];
            pWt = Wt[(size_t)(k0 + wk) * 1024 + n0 + wn];
        }
        const float* cA  = sA  + cur * 2304;
        const float* cWh = sWh + cur * 576;
        const float* cWt = sWt + cur * 576;
        #pragma unroll
        for (int k4 = 0; k4 < 8; k4++) {
            float4 a  = *(const float4*)&cA [ ty       * 36 + k4 * 4];
            float4 h0 = *(const float4*)&cWh[ tx       * 36 + k4 * 4];
            float4 h1 = *(const float4*)&cWh[(tx + 8 ) * 36 + k4 * 4];
            float4 q0 = *(const float4*)&cWt[ tx       * 36 + k4 * 4];
            float4 q1 = *(const float4*)&cWt[(tx + 8 ) * 36 + k4 * 4];
            acc4v(cH0, a, h0); acc4v(cH1, a, h1);
            acc4v(cT0, a, q0); acc4v(cT1, a, q1);
        }
        if (st < 31) {
            float* nA  = sA  + (cur ^ 1) * 2304;
            float* nWh = sWh + (cur ^ 1) * 576;
            float* nWt = sWt + (cur ^ 1) * 576;
            *(float4*)&nA[sm * 36 + sk4] = pA;
            nWh[wn * 36 + wk] = pWh;
            nWt[wn * 36 + wk] = pWt;
        }
        __syncthreads();
    }

    float sH[2] = { hsum(cH0), hsum(cH1) };
    float sT[2] = { hsum(cT0), hsum(cT1) };

    #pragma unroll
    for (int c = 0; c < 2; c++) {
        int m = m0 + ty;
        int n = n0 + tx + c * 8;
        size_t off = (size_t)m * 1024 + n;
        float addh = l0 ? addH[off] : addH[n];
        float addt = l0 ? addT[off] : addT[n];
        float so   = __ldcg(&A[off]);
        float hh   = tanhf(addh + sH[c]);
        float gg   = 1.f / (1.f + expf(-(addt + sT[c])));
        dst[off]   = (hh - so) * gg + so;
    }
}

// ---------------------------------------------------------------------------
// Projection (512-thread version): out[(b*T+t)*256+n] = S[b,:]@Wp[:,n] + bp[n]
// This CTA: rows m0..m0+63 (m0 = (bid>>6)*64), cols n0..n0+3 (n0=(bid&63)*4).
// All 512 threads stage; threads 0..255 compute (trivial work, ~1.5us).
// ---------------------------------------------------------------------------
static __device__ void proj_step(const float* __restrict__ A,
                                 const float* __restrict__ Wp,
                                 const float* __restrict__ bp,
                                 float* __restrict__ out, int t,
                                 float* sAf, float* sWp)
{
    const int tid = threadIdx.x;
    const int m0  = (blockIdx.x >> 6) * 64;
    const int n0  = (blockIdx.x & 63) * 4;
    const int rt  = tid & 63;          // output row within tile
    const int ct  = (tid >> 6) & 3;    // output col 0..3
    const int sr  = tid >> 3;          // staging row 0..63
    const int sc  = (tid & 7) * 8;     // staging k-offset (2 f4 per thread)
    float acc = 0.f;

    for (int k0 = 0; k0 < 1024; k0 += 64) {
        *(float4*)&sAf[sr * 68 + sc] =
            __ldcg((const float4*)&A[(size_t)(m0 + sr) * 1024 + k0 + sc]);
        *(float4*)&sAf[sr * 68 + sc + 4] =
            __ldcg((const float4*)&A[(size_t)(m0 + sr) * 1024 + k0 + sc + 4]);
        if (tid < 64)
            *(float4*)&sWp[tid * 4] =
                *(const float4*)&Wp[(size_t)(k0 + tid) * 256 + n0];
        __syncthreads();
        if (tid < 256) {
            #pragma unroll
            for (int k4 = 0; k4 < 16; k4++) {
                float4 a = *(const float4*)&sAf[rt * 68 + k4 * 4];
                acc += a.x * sWp[(k4 * 4 + 0) * 4 + ct];
                acc += a.y * sWp[(k4 * 4 + 1) * 4 + ct];
                acc += a.z * sWp[(k4 * 4 + 2) * 4 + ct];
                acc += a.w * sWp[(k4 * 4 + 3) * 4 + ct];
            }
        }
        __syncthreads();
    }
    if (tid < 256)
        out[((size_t)(m0 + rt) * 256 + t) * 256 + n0 + ct] = acc + bp[n0 + ct];
}

// ---------------------------------------------------------------------------
// Persistent recurrence kernel: 128 CTAs x 512 threads, 3 grid barriers/step.
// ---------------------------------------------------------------------------
__global__ __launch_bounds__(512) void recurrence_kernel(
    const float* __restrict__ Wh0s, const float* __restrict__ Wt0s,
    const float* __restrict__ Whh,  const float* __restrict__ Wth,
    const float* __restrict__ bhh,  const float* __restrict__ bth,
    const float* __restrict__ Wp,   const float* __restrict__ bp,
    float* __restrict__ out)
{
    __shared__ float sA [2 * 2304];
    __shared__ float sWh[2 * 576];
    __shared__ float sWt[2 * 576];

    int p = 0;
    for (int t = 0; t < Tc; t++) {
        // layer 0 (input-dependent adds)
        phase_step(g_s[p], g_s[p ^ 1], Wh0s, Wt0s,
                   g_xh + (size_t)t * Bc * Rc, g_xt + (size_t)t * Bc * Rc, 1,
                   sA, sWh, sWt);
        p ^= 1; gbar();
        // layer 1
        phase_step(g_s[p], g_s[p ^ 1], Whh, Wth, bhh, bth, 0, sA, sWh, sWt);
        p ^= 1; gbar();
        // layer 2
        phase_step(g_s[p], g_s[p ^ 1], Whh + 1024 * 1024, Wth + 1024 * 1024,
                   bhh + 1024, bth + 1024, 0, sA, sWh, sWt);
        p ^= 1; gbar();
        // projection of S_t: shares the barrier interval with next phase 0
        // (both only READ g_s[p]; the gbar after next phase 0 orders proj
        //  before phase 1 overwrites any buffer proj reads).
        proj_step(g_s[p], Wp, bp, out, t, sA, sWh);
        __syncthreads();   // smem handoff back to phase 0 staging
    }
}

// ---------------------------------------------------------------------------
// Host launcher (graph-capturable: 4 kernel launches total)
// ---------------------------------------------------------------------------
extern "C" void kernel_launch(void* const* d_in, const int* in_sizes, int n_in,
                              void* d_out, int out_size) {
    const int*   ids  = (const int*)  d_in[0];
    const float* emb  = (const float*)d_in[1];
    const float* Wh0x = (const float*)d_in[2];
    const float* Wh0s = (const float*)d_in[3];
    const float* bh0  = (const float*)d_in[4];
    const float* Wt0x = (const float*)d_in[5];
    const float* Wt0s = (const float*)d_in[6];
    const float* bt0  = (const float*)d_in[7];
    const float* Whh  = (const float*)d_in[8];    // [2,1024,1024]
    const float* bhh  = (const float*)d_in[9];    // [2,1024]
    const float* Wth  = (const float*)d_in[10];
    const float* bth  = (const float*)d_in[11];
    const float* Wp   = (const float*)d_in[12];   // [1024,256]
    const float* bp   = (const float*)d_in[13];
    float* out = (float*)d_out;

    zero_kernel  <<<128, 256>>>();
    gather_kernel<<<8192, 256>>>(ids, emb);
    prologue_kernel<<<dim3(64, 512), 256>>>(Wh0x, Wt0x, bh0, bt0);
    recurrence_kernel<<<128, 512>>>(Wh0s, Wt0s, Whh, Wth, bhh, bth, Wp, bp, out);
}

// round 12
// speedup vs baseline: 1.4459x; 1.4459x over previous
#include <cuda_runtime.h>
#include <math.h>

// Problem constants
static const int Bc  = 128;    // batch
static const int Tc  = 256;    // time steps
static const int Rc  = 1024;   // recurrent width

// ---------------------------------------------------------------------------
// Device scratch (no allocations allowed -> __device__ globals)
// ---------------------------------------------------------------------------
__device__ float g_x [32768 * 256];      // gathered embeddings, row = t*B + b
__device__ float g_xh[33554432];         // xh[t*B+b][r]  (x@Wh0x + bh0)
__device__ float g_xt[33554432];         // xt[t*B+b][r]  (x@Wt0x + bt0)
__device__ float g_s [2][128 * 1024];    // ping-pong state, row-major [b][r]
__device__ unsigned g_cnt = 0;           // grid barrier arrival counter
__device__ unsigned g_gen = 0;           // grid barrier generation

// 4-wide multiply-accumulate (function, NOT a macro: a macro parameter named
// `w` would capture the `.w` member token and break expansion).
static __device__ __forceinline__ void acc4(float& acc, const float4& a,
                                            const float4& b) {
    acc += a.x * b.x;
    acc += a.y * b.y;
    acc += a.z * b.z;
    acc += a.w * b.w;
}

// Software grid barrier for a co-resident 128-CTA persistent kernel.
static __device__ __forceinline__ void gbar() {
    __threadfence();
    __syncthreads();
    if (threadIdx.x == 0) {
        unsigned g = *((volatile unsigned*)&g_gen);
        if (atomicAdd(&g_cnt, 1) == gridDim.x - 1) {
            g_cnt = 0;
            __threadfence();
            atomicAdd(&g_gen, 1);
        } else {
            while (*((volatile unsigned*)&g_gen) == g) { }
        }
    }
    __syncthreads();
    __threadfence();
}

// ---------------------------------------------------------------------------
// Zero the initial state
// ---------------------------------------------------------------------------
__global__ void zero_kernel() {
    int i = blockIdx.x * 256 + threadIdx.x;          // 32768 float4
    ((float4*)g_s[0])[i] = make_float4(0.f, 0.f, 0.f, 0.f);
}

// ---------------------------------------------------------------------------
// Embedding gather: g_x[t*B+b][0:256] = emb[ids[b*T+t]][0:256]
// ---------------------------------------------------------------------------
__global__ void gather_kernel(const int* __restrict__ ids,
                              const float* __restrict__ emb) {
    int idx = blockIdx.x * 256 + threadIdx.x;        // 32768 rows * 64 f4
    int row = idx >> 6;
    int c   = (idx & 63) << 2;
    int t = row >> 7;            // B = 128
    int b = row & 127;
    int id = ids[b * Tc + t];
    *(float4*)&g_x[(size_t)row * 256 + c] =
        *(const float4*)&emb[(size_t)id * 256 + c];
}

// ---------------------------------------------------------------------------
// Prologue dual GEMM: xh = x@Whx + bh ; xt = x@Wtx + bt  (unchanged, works)
// ---------------------------------------------------------------------------
__global__ __launch_bounds__(256) void prologue_kernel(
    const float* __restrict__ Whx, const float* __restrict__ Wtx,
    const float* __restrict__ bh,  const float* __restrict__ bt) {
    __shared__ float sA [2][64 * 36];
    __shared__ float sWh[2][16 * 36];
    __shared__ float sWt[2][16 * 36];

    const int tid = threadIdx.x;
    const int tx  = tid & 7;
    const int ty  = tid >> 3;
    const int n0  = blockIdx.x * 16;
    const int m0  = blockIdx.y * 64;
    const int LDA = 256, LDW = 1024;

    const int sm  = tid >> 3;
    const int sk4 = (tid & 7) * 4;
    const int wn  = tid & 15;
    const int wk  = tid >> 4;

    float aH[2][2] = {{0.f,0.f},{0.f,0.f}};
    float aT[2][2] = {{0.f,0.f},{0.f,0.f}};

    #pragma unroll
    for (int r = 0; r < 2; r++) {
        int m = sm + r * 32;
        *(float4*)&sA[0][m * 36 + sk4] =
            *(const float4*)&g_x[(size_t)(m0 + m) * LDA + sk4];
    }
    #pragma unroll
    for (int r = 0; r < 2; r++) {
        int kk = wk + r * 16;
        sWh[0][wn * 36 + kk] = Whx[(size_t)kk * LDW + n0 + wn];
        sWt[0][wn * 36 + kk] = Wtx[(size_t)kk * LDW + n0 + wn];
    }
    __syncthreads();

    const int NS = 256 / 32;
    for (int st = 0; st < NS; st++) {
        const int cur = st & 1;
        float4 pA0, pA1; float pWh0, pWh1, pWt0, pWt1;
        if (st + 1 < NS) {
            int k0 = (st + 1) * 32;
            pA0 = *(const float4*)&g_x[(size_t)(m0 + sm     ) * LDA + k0 + sk4];
            pA1 = *(const float4*)&g_x[(size_t)(m0 + sm + 32) * LDA + k0 + sk4];
            pWh0 = Whx[(size_t)(k0 + wk     ) * LDW + n0 + wn];
            pWh1 = Whx[(size_t)(k0 + wk + 16) * LDW + n0 + wn];
            pWt0 = Wtx[(size_t)(k0 + wk     ) * LDW + n0 + wn];
            pWt1 = Wtx[(size_t)(k0 + wk + 16) * LDW + n0 + wn];
        }
        #pragma unroll
        for (int k4 = 0; k4 < 8; k4++) {
            float4 a0 = *(const float4*)&sA [cur][ ty       * 36 + k4 * 4];
            float4 a1 = *(const float4*)&sA [cur][(ty + 32) * 36 + k4 * 4];
            float4 h0 = *(const float4*)&sWh[cur][ tx       * 36 + k4 * 4];
            float4 h1 = *(const float4*)&sWh[cur][(tx + 8 ) * 36 + k4 * 4];
            float4 q0 = *(const float4*)&sWt[cur][ tx       * 36 + k4 * 4];
            float4 q1 = *(const float4*)&sWt[cur][(tx + 8 ) * 36 + k4 * 4];
            acc4(aH[0][0], a0, h0); acc4(aH[0][1], a0, h1);
            acc4(aH[1][0], a1, h0); acc4(aH[1][1], a1, h1);
            acc4(aT[0][0], a0, q0); acc4(aT[0][1], a0, q1);
            acc4(aT[1][0], a1, q0); acc4(aT[1][1], a1, q1);
        }
        if (st + 1 < NS) {
            int nb = cur ^ 1;
            *(float4*)&sA[nb][ sm       * 36 + sk4] = pA0;
            *(float4*)&sA[nb][(sm + 32) * 36 + sk4] = pA1;
            sWh[nb][wn * 36 + wk     ] = pWh0;
            sWh[nb][wn * 36 + wk + 16] = pWh1;
            sWt[nb][wn * 36 + wk     ] = pWt0;
            sWt[nb][wn * 36 + wk + 16] = pWt1;
        }
        __syncthreads();
    }

    #pragma unroll
    for (int r = 0; r < 2; r++)
        #pragma unroll
        for (int c = 0; c < 2; c++) {
            int m = m0 + ty + r * 32;
            int n = n0 + tx + c * 8;
            g_xh[(size_t)m * 1024 + n] = aH[r][c] + bh[n];
            g_xt[(size_t)m * 1024 + n] = aT[r][c] + bt[n];
        }
}

// ---------------------------------------------------------------------------
// One highway phase, split-K rebalanced version:
//   h = tanh(addH + s@Wh);  g = sigmoid(addT + s@Wt);  s' = (h - s)*g + s
// Grid 128 CTAs: m-tile = bid>>5 (32 rows), n-tile = bid&31 (32 n-cols).
// 256 threads = 2 split-K halves x (8 m-groups x 16 col-groups).
// Per thread: 4 rows x (2 H-cols + 2 T-cols) = 16 fp32 accumulators.
// Smem pool layout (floats):  sA [2kp][32][36] @ 0
//                             sWh[2kp][32][36] @ 2304
//                             sWt[2kp][32][36] @ 4608
//                             sRed[2kp][2048]  @ 0 (aliases sA/sWh, post-sync)
// ---------------------------------------------------------------------------
static __device__ void phase_step(
    const float* __restrict__ A, float* __restrict__ dst,
    const float* __restrict__ Wh, const float* __restrict__ Wt,
    const float* __restrict__ addH, const float* __restrict__ addT, int l0,
    float* smp)
{
    const int tid = threadIdx.x;
    const int kp  = tid >> 7;          // split-K half (warp-aligned)
    const int u   = tid & 127;
    const int mg  = u >> 4;            // 0..7  (4 rows each)
    const int cg  = u & 15;            // 0..15 (cols cg and cg+16)
    const int m0  = (blockIdx.x >> 5) * 32;
    const int n0  = (blockIdx.x & 31) * 32;

    float* sA  = smp +        kp * 1152;
    float* sWh = smp + 2304 + kp * 1152;
    float* sWt = smp + 4608 + kp * 1152;

    // staging maps (per split half: A 32x32, W 32x32 each)
    const int ar0 = (u * 2    ) >> 3, ac0 = ((u * 2    ) & 7) * 4;
    const int ar1 = (u * 2 + 1) >> 3, ac1 = ((u * 2 + 1) & 7) * 4;
    const int wn  = u & 31;
    const int wkb = (u >> 5) * 8;

    const int gk0 = kp * 512;

    float acc[4][4];
    #pragma unroll
    for (int r = 0; r < 4; r++)
        #pragma unroll
        for (int c = 0; c < 4; c++) acc[r][c] = 0.f;

    // prefetch stage 0 into registers
    float4 rA0 = __ldcg((const float4*)&A[(size_t)(m0 + ar0) * 1024 + gk0 + ac0]);
    float4 rA1 = __ldcg((const float4*)&A[(size_t)(m0 + ar1) * 1024 + gk0 + ac1]);
    float rWh[8], rWt[8];
    #pragma unroll
    for (int j = 0; j < 8; j++) {
        rWh[j] = Wh[(size_t)(gk0 + wkb + j) * 1024 + n0 + wn];
        rWt[j] = Wt[(size_t)(gk0 + wkb + j) * 1024 + n0 + wn];
    }

    for (int st = 0; st < 16; st++) {
        __syncthreads();               // previous-stage consumers done
        *(float4*)&sA[ar0 * 36 + ac0] = rA0;
        *(float4*)&sA[ar1 * 36 + ac1] = rA1;
        #pragma unroll
        for (int j = 0; j < 8; j++) {
            sWh[wn * 36 + wkb + j] = rWh[j];
            sWt[wn * 36 + wkb + j] = rWt[j];
        }
        __syncthreads();               // staging visible
        if (st < 15) {                 // prefetch next stage (hidden by compute)
            int k0 = gk0 + (st + 1) * 32;
            rA0 = __ldcg((const float4*)&A[(size_t)(m0 + ar0) * 1024 + k0 + ac0]);
            rA1 = __ldcg((const float4*)&A[(size_t)(m0 + ar1) * 1024 + k0 + ac1]);
            #pragma unroll
            for (int j = 0; j < 8; j++) {
                rWh[j] = Wh[(size_t)(k0 + wkb + j) * 1024 + n0 + wn];
                rWt[j] = Wt[(size_t)(k0 + wkb + j) * 1024 + n0 + wn];
            }
        }
        #pragma unroll
        for (int c4 = 0; c4 < 8; c4++) {
            float4 a0 = *(const float4*)&sA[(mg * 4 + 0) * 36 + c4 * 4];
            float4 a1 = *(const float4*)&sA[(mg * 4 + 1) * 36 + c4 * 4];
            float4 a2 = *(const float4*)&sA[(mg * 4 + 2) * 36 + c4 * 4];
            float4 a3 = *(const float4*)&sA[(mg * 4 + 3) * 36 + c4 * 4];
            float4 h0 = *(const float4*)&sWh[ cg       * 36 + c4 * 4];
            float4 h1 = *(const float4*)&sWh[(cg + 16) * 36 + c4 * 4];
            float4 t0 = *(const float4*)&sWt[ cg       * 36 + c4 * 4];
            float4 t1 = *(const float4*)&sWt[(cg + 16) * 36 + c4 * 4];
            acc4(acc[0][0], a0, h0); acc4(acc[0][1], a0, h1);
            acc4(acc[0][2], a0, t0); acc4(acc[0][3], a0, t1);
            acc4(acc[1][0], a1, h0); acc4(acc[1][1], a1, h1);
            acc4(acc[1][2], a1, t0); acc4(acc[1][3], a1, t1);
            acc4(acc[2][0], a2, h0); acc4(acc[2][1], a2, h1);
            acc4(acc[2][2], a2, t0); acc4(acc[2][3], a2, t1);
            acc4(acc[3][0], a3, h0); acc4(acc[3][1], a3, h1);
            acc4(acc[3][2], a3, t0); acc4(acc[3][3], a3, t1);
        }
    }

    __syncthreads();                   // all compute done before aliasing smem

    // split-K reduction staging: sRed[kp][gate][row][ncol]
    #pragma unroll
    for (int rr = 0; rr < 4; rr++) {
        int row = mg * 4 + rr;
        smp[kp * 2048 +        row * 32 + cg     ] = acc[rr][0];
        smp[kp * 2048 +        row * 32 + cg + 16] = acc[rr][1];
        smp[kp * 2048 + 1024 + row * 32 + cg     ] = acc[rr][2];
        smp[kp * 2048 + 1024 + row * 32 + cg + 16] = acc[rr][3];
    }
    __syncthreads();

    // epilogue: 1024 state outputs, 4 per thread
    #pragma unroll
    for (int i = 0; i < 4; i++) {
        int p2  = tid * 4 + i;
        int row = p2 >> 5, ncol = p2 & 31;
        int m = m0 + row, n = n0 + ncol;
        size_t off = (size_t)m * 1024 + n;
        float H = smp[       row * 32 + ncol] + smp[2048 +        row * 32 + ncol];
        float T = smp[1024 + row * 32 + ncol] + smp[2048 + 1024 + row * 32 + ncol];
        float addh = l0 ? addH[off] : addH[n];
        float addt = l0 ? addT[off] : addT[n];
        float so   = __ldcg(&A[off]);
        float hh   = tanhf(addh + H);
        float gg   = 1.f / (1.f + expf(-(addt + T)));
        dst[off]   = (hh - so) * gg + so;
    }
}

// ---------------------------------------------------------------------------
// Projection: out[(b*T+t)*256+n] = S[b,:]@Wp[:,n] + bp[n]   (R10 version)
// This CTA: rows m0..m0+63 (m0 = (bid>>6)*64), cols n0..n0+3 (n0=(bid&63)*4).
// ---------------------------------------------------------------------------
static __device__ void proj_step(const float* __restrict__ A,
                                 const float* __restrict__ Wp,
                                 const float* __restrict__ bp,
                                 float* __restrict__ out, int t,
                                 float* smp)
{
    float* sAf = smp;              // 64*68 = 4352 floats
    float* sWp = smp + 4352;       // 256 floats
    const int tid = threadIdx.x;
    const int m0  = (blockIdx.x >> 6) * 64;
    const int n0  = (blockIdx.x & 63) * 4;
    const int rt  = tid & 63;
    const int ct  = tid >> 6;          // 0..3
    const int sr  = tid >> 2;          // 0..63
    const int sc  = (tid & 3) * 16;
    float acc = 0.f;

    for (int k0 = 0; k0 < 1024; k0 += 64) {
        #pragma unroll
        for (int i = 0; i < 4; i++)
            *(float4*)&sAf[sr * 68 + sc + i * 4] =
                __ldcg((const float4*)&A[(size_t)(m0 + sr) * 1024 + k0 + sc + i * 4]);
        if (tid < 64)
            *(float4*)&sWp[tid * 4] =
                *(const float4*)&Wp[(size_t)(k0 + tid) * 256 + n0];
        __syncthreads();
        #pragma unroll
        for (int k4 = 0; k4 < 16; k4++) {
            float4 a = *(const float4*)&sAf[rt * 68 + k4 * 4];
            acc += a.x * sWp[(k4 * 4 + 0) * 4 + ct];
            acc += a.y * sWp[(k4 * 4 + 1) * 4 + ct];
            acc += a.z * sWp[(k4 * 4 + 2) * 4 + ct];
            acc += a.w * sWp[(k4 * 4 + 3) * 4 + ct];
        }
        __syncthreads();
    }
    out[((size_t)(m0 + rt) * 256 + t) * 256 + n0 + ct] = acc + bp[n0 + ct];
}

// ---------------------------------------------------------------------------
// Persistent recurrence kernel: 128 CTAs x 256 threads, 3 grid barriers/step.
// ---------------------------------------------------------------------------
__global__ __launch_bounds__(256) void recurrence_kernel(
    const float* __restrict__ Wh0s, const float* __restrict__ Wt0s,
    const float* __restrict__ Whh,  const float* __restrict__ Wth,
    const float* __restrict__ bhh,  const float* __restrict__ bth,
    const float* __restrict__ Wp,   const float* __restrict__ bp,
    float* __restrict__ out)
{
    __shared__ float smp[6912];       // 27.6 KB pool

    int p = 0;
    for (int t = 0; t < Tc; t++) {
        // layer 0 (input-dependent adds)
        phase_step(g_s[p], g_s[p ^ 1], Wh0s, Wt0s,
                   g_xh + (size_t)t * Bc * Rc, g_xt + (size_t)t * Bc * Rc, 1,
                   smp);
        p ^= 1; gbar();
        // layer 1
        phase_step(g_s[p], g_s[p ^ 1], Whh, Wth, bhh, bth, 0, smp);
        p ^= 1; gbar();
        // layer 2
        phase_step(g_s[p], g_s[p ^ 1], Whh + 1024 * 1024, Wth + 1024 * 1024,
                   bhh + 1024, bth + 1024, 0, smp);
        p ^= 1; gbar();
        // projection of S_t (reads only g_s[p]; safe until phase 1 of t+1)
        proj_step(g_s[p], Wp, bp, out, t, smp);
        __syncthreads();   // smem handoff back to phase 0 staging
    }
}

// ---------------------------------------------------------------------------
// Host launcher (graph-capturable: 4 kernel launches total)
// ---------------------------------------------------------------------------
extern "C" void kernel_launch(void* const* d_in, const int* in_sizes, int n_in,
                              void* d_out, int out_size) {
    const int*   ids  = (const int*)  d_in[0];
    const float* emb  = (const float*)d_in[1];
    const float* Wh0x = (const float*)d_in[2];
    const float* Wh0s = (const float*)d_in[3];
    const float* bh0  = (const float*)d_in[4];
    const float* Wt0x = (const float*)d_in[5];
    const float* Wt0s = (const float*)d_in[6];
    const float* bt0  = (const float*)d_in[7];
    const float* Whh  = (const float*)d_in[8];    // [2,1024,1024]
    const float* bhh  = (const float*)d_in[9];    // [2,1024]
    const float* Wth  = (const float*)d_in[10];
    const float* bth  = (const float*)d_in[11];
    const float* Wp   = (const float*)d_in[12];   // [1024,256]
    const float* bp   = (const float*)d_in[13];
    float* out = (float*)d_out;

    zero_kernel  <<<128, 256>>>();
    gather_kernel<<<8192, 256>>>(ids, emb);
    prologue_kernel<<<dim3(64, 512), 256>>>(Wh0x, Wt0x, bh0, bt0);
    recurrence_kernel<<<128, 256>>>(Wh0s, Wt0s, Whh, Wth, bhh, bth, Wp, bp, out);
}

// round 13
// speedup vs baseline: 1.5936x; 1.1022x over previous
#include <cuda_runtime.h>
#include <math.h>

// Problem constants
static const int Bc  = 128;    // batch
static const int Tc  = 256;    // time steps
static const int Rc  = 1024;   // recurrent width

// ---------------------------------------------------------------------------
// Device scratch (no allocations allowed -> __device__ globals)
// ---------------------------------------------------------------------------
__device__ float g_x [32768 * 256];      // gathered embeddings, row = t*B + b
__device__ float g_xh[33554432];         // xh[t*B+b][r]  (x@Wh0x + bh0)
__device__ float g_xt[33554432];         // xt[t*B+b][r]  (x@Wt0x + bt0)
__device__ float g_s [2][128 * 1024];    // ping-pong state, row-major [b][r]
__device__ unsigned g_cnt = 0;           // grid barrier arrival counter
__device__ unsigned g_gen = 0;           // grid barrier generation

// 4-wide multiply-accumulate (function, NOT a macro: a macro parameter named
// `w` would capture the `.w` member token and break expansion).
static __device__ __forceinline__ void acc4(float& acc, const float4& a,
                                            const float4& b) {
    acc += a.x * b.x;
    acc += a.y * b.y;
    acc += a.z * b.z;
    acc += a.w * b.w;
}

// ---- packed fp32x2 helpers (FFMA2 path; ptxas only emits via PTX) ----------
static __device__ __forceinline__ unsigned long long pk2(float x) {
    unsigned long long r;
    asm("mov.b64 %0, {%1, %1};" : "=l"(r) : "f"(x));
    return r;
}
static __device__ __forceinline__ void fma2(unsigned long long& d,
                                            unsigned long long a,
                                            unsigned long long b) {
    asm("fma.rn.f32x2 %0, %1, %2, %0;" : "+l"(d) : "l"(a), "l"(b));
}
static __device__ __forceinline__ void upk2(float& lo, float& hi,
                                            unsigned long long v) {
    asm("mov.b64 {%0, %1}, %2;" : "=f"(lo), "=f"(hi) : "l"(v));
}

// Software grid barrier for a co-resident 128-CTA persistent kernel.
static __device__ __forceinline__ void gbar() {
    __threadfence();
    __syncthreads();
    if (threadIdx.x == 0) {
        unsigned g = *((volatile unsigned*)&g_gen);
        if (atomicAdd(&g_cnt, 1) == gridDim.x - 1) {
            g_cnt = 0;
            __threadfence();
            atomicAdd(&g_gen, 1);
        } else {
            while (*((volatile unsigned*)&g_gen) == g) { }
        }
    }
    __syncthreads();
    __threadfence();
}

// ---------------------------------------------------------------------------
// Zero the initial state
// ---------------------------------------------------------------------------
__global__ void zero_kernel() {
    int i = blockIdx.x * 256 + threadIdx.x;          // 32768 float4
    ((float4*)g_s[0])[i] = make_float4(0.f, 0.f, 0.f, 0.f);
}

// ---------------------------------------------------------------------------
// Embedding gather: g_x[t*B+b][0:256] = emb[ids[b*T+t]][0:256]
// ---------------------------------------------------------------------------
__global__ void gather_kernel(const int* __restrict__ ids,
                              const float* __restrict__ emb) {
    int idx = blockIdx.x * 256 + threadIdx.x;        // 32768 rows * 64 f4
    int row = idx >> 6;
    int c   = (idx & 63) << 2;
    int t = row >> 7;            // B = 128
    int b = row & 127;
    int id = ids[b * Tc + t];
    *(float4*)&g_x[(size_t)row * 256 + c] =
        *(const float4*)&emb[(size_t)id * 256 + c];
}

// ---------------------------------------------------------------------------
// Prologue dual GEMM: xh = x@Whx + bh ; xt = x@Wtx + bt  (unchanged, works)
// ---------------------------------------------------------------------------
__global__ __launch_bounds__(256) void prologue_kernel(
    const float* __restrict__ Whx, const float* __restrict__ Wtx,
    const float* __restrict__ bh,  const float* __restrict__ bt) {
    __shared__ float sA [2][64 * 36];
    __shared__ float sWh[2][16 * 36];
    __shared__ float sWt[2][16 * 36];

    const int tid = threadIdx.x;
    const int tx  = tid & 7;
    const int ty  = tid >> 3;
    const int n0  = blockIdx.x * 16;
    const int m0  = blockIdx.y * 64;
    const int LDA = 256, LDW = 1024;

    const int sm  = tid >> 3;
    const int sk4 = (tid & 7) * 4;
    const int wn  = tid & 15;
    const int wk  = tid >> 4;

    float aH[2][2] = {{0.f,0.f},{0.f,0.f}};
    float aT[2][2] = {{0.f,0.f},{0.f,0.f}};

    #pragma unroll
    for (int r = 0; r < 2; r++) {
        int m = sm + r * 32;
        *(float4*)&sA[0][m * 36 + sk4] =
            *(const float4*)&g_x[(size_t)(m0 + m) * LDA + sk4];
    }
    #pragma unroll
    for (int r = 0; r < 2; r++) {
        int kk = wk + r * 16;
        sWh[0][wn * 36 + kk] = Whx[(size_t)kk * LDW + n0 + wn];
        sWt[0][wn * 36 + kk] = Wtx[(size_t)kk * LDW + n0 + wn];
    }
    __syncthreads();

    const int NS = 256 / 32;
    for (int st = 0; st < NS; st++) {
        const int cur = st & 1;
        float4 pA0, pA1; float pWh0, pWh1, pWt0, pWt1;
        if (st + 1 < NS) {
            int k0 = (st + 1) * 32;
            pA0 = *(const float4*)&g_x[(size_t)(m0 + sm     ) * LDA + k0 + sk4];
            pA1 = *(const float4*)&g_x[(size_t)(m0 + sm + 32) * LDA + k0 + sk4];
            pWh0 = Whx[(size_t)(k0 + wk     ) * LDW + n0 + wn];
            pWh1 = Whx[(size_t)(k0 + wk + 16) * LDW + n0 + wn];
            pWt0 = Wtx[(size_t)(k0 + wk     ) * LDW + n0 + wn];
            pWt1 = Wtx[(size_t)(k0 + wk + 16) * LDW + n0 + wn];
        }
        #pragma unroll
        for (int k4 = 0; k4 < 8; k4++) {
            float4 a0 = *(const float4*)&sA [cur][ ty       * 36 + k4 * 4];
            float4 a1 = *(const float4*)&sA [cur][(ty + 32) * 36 + k4 * 4];
            float4 h0 = *(const float4*)&sWh[cur][ tx       * 36 + k4 * 4];
            float4 h1 = *(const float4*)&sWh[cur][(tx + 8 ) * 36 + k4 * 4];
            float4 q0 = *(const float4*)&sWt[cur][ tx       * 36 + k4 * 4];
            float4 q1 = *(const float4*)&sWt[cur][(tx + 8 ) * 36 + k4 * 4];
            acc4(aH[0][0], a0, h0); acc4(aH[0][1], a0, h1);
            acc4(aH[1][0], a1, h0); acc4(aH[1][1], a1, h1);
            acc4(aT[0][0], a0, q0); acc4(aT[0][1], a0, q1);
            acc4(aT[1][0], a1, q0); acc4(aT[1][1], a1, q1);
        }
        if (st + 1 < NS) {
            int nb = cur ^ 1;
            *(float4*)&sA[nb][ sm       * 36 + sk4] = pA0;
            *(float4*)&sA[nb][(sm + 32) * 36 + sk4] = pA1;
            sWh[nb][wn * 36 + wk     ] = pWh0;
            sWh[nb][wn * 36 + wk + 16] = pWh1;
            sWt[nb][wn * 36 + wk     ] = pWt0;
            sWt[nb][wn * 36 + wk + 16] = pWt1;
        }
        __syncthreads();
    }

    #pragma unroll
    for (int r = 0; r < 2; r++)
        #pragma unroll
        for (int c = 0; c < 2; c++) {
            int m = m0 + ty + r * 32;
            int n = n0 + tx + c * 8;
            g_xh[(size_t)m * 1024 + n] = aH[r][c] + bh[n];
            g_xt[(size_t)m * 1024 + n] = aT[r][c] + bt[n];
        }
}

// ---------------------------------------------------------------------------
// One highway phase, FFMA2 + 4-way split-K version (512 threads):
//   h = tanh(addH + s@Wh);  g = sigmoid(addT + s@Wt);  s' = (h - s)*g + s
// Grid 128 CTAs: m-tile = bid>>5 (32 rows), n-tile = bid&31 (32 n-cols).
// tid>>7 = kp (split-K quarter, 256 k each, KC=16 per stage -> 16 stages).
// Worker u=tid&127: mg=u>>4 -> rows mg*4..+3; cg=u&15 -> packed col pair
// (n0+cg, n0+cg+16) for both gates. Accumulators: 8 x f32x2 (16 scalars).
// W staged PAIR-INTERLEAVED in smem: sW[cg][k] = {W[k][n0+cg], W[k][n0+cg+16]}
// so the b64 MMA operand loads directly (no packing); A broadcast via mov.b64.
// Smem pool (floats): staging kp*1792 (sA 640 | sWh 576 | sWt 576) = 7168;
// aliased post-sync by red[kp][gate][32][32] = 8192. Pool = 8192 f (32 KB).
// ---------------------------------------------------------------------------
static __device__ void phase_step(
    const float* __restrict__ A, float* __restrict__ dst,
    const float* __restrict__ Wh, const float* __restrict__ Wt,
    const float* __restrict__ addH, const float* __restrict__ addT, int l0,
    float* smp)
{
    const int tid = threadIdx.x;
    const int kp  = tid >> 7;
    const int u   = tid & 127;
    const int mg  = u >> 4;            // 0..7
    const int cg  = u & 15;            // 0..15
    const int m0  = (blockIdx.x >> 5) * 32;
    const int n0  = (blockIdx.x & 31) * 32;

    float* sA  = smp + kp * 1792;          // 32 rows x 16 k, stride 20
    float* sWh = smp + kp * 1792 + 640;    // 16 paircols x 16 k x 2, stride 36
    float* sWt = smp + kp * 1792 + 1216;

    const int ar  = u >> 2;            // A staging row 0..31
    const int akc = (u & 3) * 4;       // A staging k offset
    const int wk  = u >> 4;            // W staging k rows wk, wk+8
    const int gk0 = kp * 256;

    unsigned long long aH[4] = {0ull,0ull,0ull,0ull};
    unsigned long long aT[4] = {0ull,0ull,0ull,0ull};

    // prefetch stage 0
    float4 rA = __ldcg((const float4*)&A[(size_t)(m0 + ar) * 1024 + gk0 + akc]);
    float rh[4], rq[4];
    rh[0] = Wh[(size_t)(gk0 + wk    ) * 1024 + n0 + cg     ];
    rh[1] = Wh[(size_t)(gk0 + wk    ) * 1024 + n0 + cg + 16];
    rh[2] = Wh[(size_t)(gk0 + wk + 8) * 1024 + n0 + cg     ];
    rh[3] = Wh[(size_t)(gk0 + wk + 8) * 1024 + n0 + cg + 16];
    rq[0] = Wt[(size_t)(gk0 + wk    ) * 1024 + n0 + cg     ];
    rq[1] = Wt[(size_t)(gk0 + wk    ) * 1024 + n0 + cg + 16];
    rq[2] = Wt[(size_t)(gk0 + wk + 8) * 1024 + n0 + cg     ];
    rq[3] = Wt[(size_t)(gk0 + wk + 8) * 1024 + n0 + cg + 16];

    for (int st = 0; st < 16; st++) {
        __syncthreads();               // previous-stage consumers done
        *(float4*)&sA[ar * 20 + akc] = rA;
        *(float2*)&sWh[cg * 36 + 2 * wk      ] = make_float2(rh[0], rh[1]);
        *(float2*)&sWh[cg * 36 + 2 * (wk + 8)] = make_float2(rh[2], rh[3]);
        *(float2*)&sWt[cg * 36 + 2 * wk      ] = make_float2(rq[0], rq[1]);
        *(float2*)&sWt[cg * 36 + 2 * (wk + 8)] = make_float2(rq[2], rq[3]);
        __syncthreads();               // staging visible
        if (st < 15) {                 // prefetch next stage (hidden by compute)
            int k0 = gk0 + (st + 1) * 16;
            rA = __ldcg((const float4*)&A[(size_t)(m0 + ar) * 1024 + k0 + akc]);
            rh[0] = Wh[(size_t)(k0 + wk    ) * 1024 + n0 + cg     ];
            rh[1] = Wh[(size_t)(k0 + wk    ) * 1024 + n0 + cg + 16];
            rh[2] = Wh[(size_t)(k0 + wk + 8) * 1024 + n0 + cg     ];
            rh[3] = Wh[(size_t)(k0 + wk + 8) * 1024 + n0 + cg + 16];
            rq[0] = Wt[(size_t)(k0 + wk    ) * 1024 + n0 + cg     ];
            rq[1] = Wt[(size_t)(k0 + wk    ) * 1024 + n0 + cg + 16];
            rq[2] = Wt[(size_t)(k0 + wk + 8) * 1024 + n0 + cg     ];
            rq[3] = Wt[(size_t)(k0 + wk + 8) * 1024 + n0 + cg + 16];
        }
        #pragma unroll
        for (int c4 = 0; c4 < 4; c4++) {
            // b64 pairs for k = 4*c4 .. 4*c4+3 (pair j at float 2j)
            ulonglong2 h01 = *(const ulonglong2*)&sWh[cg * 36 + 8 * c4    ];
            ulonglong2 h23 = *(const ulonglong2*)&sWh[cg * 36 + 8 * c4 + 4];
            ulonglong2 q01 = *(const ulonglong2*)&sWt[cg * 36 + 8 * c4    ];
            ulonglong2 q23 = *(const ulonglong2*)&sWt[cg * 36 + 8 * c4 + 4];
            #pragma unroll
            for (int rr = 0; rr < 4; rr++) {
                float4 av = *(const float4*)&sA[(mg * 4 + rr) * 20 + 4 * c4];
                unsigned long long p;
                p = pk2(av.x); fma2(aH[rr], p, h01.x); fma2(aT[rr], p, q01.x);
                p = pk2(av.y); fma2(aH[rr], p, h01.y); fma2(aT[rr], p, q01.y);
                p = pk2(av.z); fma2(aH[rr], p, h23.x); fma2(aT[rr], p, q23.x);
                p = pk2(av.w); fma2(aH[rr], p, h23.y); fma2(aT[rr], p, q23.y);
            }
        }
    }
    __syncthreads();                   // all compute done before aliasing smem

    // split-K reduction staging: red[kp][gate][row32][col32]
    #pragma unroll
    for (int rr = 0; rr < 4; rr++) {
        int row = mg * 4 + rr;
        float lo, hi;
        upk2(lo, hi, aH[rr]);
        smp[kp * 2048 +        row * 32 + cg     ] = lo;
        smp[kp * 2048 +        row * 32 + cg + 16] = hi;
        upk2(lo, hi, aT[rr]);
        smp[kp * 2048 + 1024 + row * 32 + cg     ] = lo;
        smp[kp * 2048 + 1024 + row * 32 + cg + 16] = hi;
    }
    __syncthreads();

    // epilogue: 1024 state outputs, 2 per thread
    #pragma unroll
    for (int i = 0; i < 2; i++) {
        int p2  = tid * 2 + i;
        int row = p2 >> 5, col = p2 & 31;
        float H = smp[       row * 32 + col] + smp[2048 +        row * 32 + col]
                + smp[4096 + row * 32 + col] + smp[6144 +        row * 32 + col];
        float T = smp[1024 + row * 32 + col] + smp[3072 +        row * 32 + col]
                + smp[5120 + row * 32 + col] + smp[7168 +        row * 32 + col];
        int m = m0 + row, n = n0 + col;
        size_t off = (size_t)m * 1024 + n;
        float addh = l0 ? addH[off] : addH[n];
        float addt = l0 ? addT[off] : addT[n];
        float so   = __ldcg(&A[off]);
        float hh   = tanhf(addh + H);
        float gg   = 1.f / (1.f + expf(-(addt + T)));
        dst[off]   = (hh - so) * gg + so;
    }
}

// ---------------------------------------------------------------------------
// Projection (512-thread, validated in R11): out[(b*T+t)*256+n] = S@Wp + bp
// This CTA: rows m0..m0+63 (m0 = (bid>>6)*64), cols n0..n0+3 (n0=(bid&63)*4).
// All 512 threads stage; threads 0..255 compute.
// ---------------------------------------------------------------------------
static __device__ void proj_step(const float* __restrict__ A,
                                 const float* __restrict__ Wp,
                                 const float* __restrict__ bp,
                                 float* __restrict__ out, int t,
                                 float* smp)
{
    float* sAf = smp;              // 64*68 = 4352 floats
    float* sWp = smp + 4352;       // 256 floats
    const int tid = threadIdx.x;
    const int m0  = (blockIdx.x >> 6) * 64;
    const int n0  = (blockIdx.x & 63) * 4;
    const int rt  = tid & 63;          // output row within tile
    const int ct  = (tid >> 6) & 3;    // output col 0..3
    const int sr  = tid >> 3;          // staging row 0..63
    const int sc  = (tid & 7) * 8;     // staging k-offset (2 f4 per thread)
    float acc = 0.f;

    for (int k0 = 0; k0 < 1024; k0 += 64) {
        *(float4*)&sAf[sr * 68 + sc] =
            __ldcg((const float4*)&A[(size_t)(m0 + sr) * 1024 + k0 + sc]);
        *(float4*)&sAf[sr * 68 + sc + 4] =
            __ldcg((const float4*)&A[(size_t)(m0 + sr) * 1024 + k0 + sc + 4]);
        if (tid < 64)
            *(float4*)&sWp[tid * 4] =
                *(const float4*)&Wp[(size_t)(k0 + tid) * 256 + n0];
        __syncthreads();
        if (tid < 256) {
            #pragma unroll
            for (int k4 = 0; k4 < 16; k4++) {
                float4 a = *(const float4*)&sAf[rt * 68 + k4 * 4];
                acc += a.x * sWp[(k4 * 4 + 0) * 4 + ct];
                acc += a.y * sWp[(k4 * 4 + 1) * 4 + ct];
                acc += a.z * sWp[(k4 * 4 + 2) * 4 + ct];
                acc += a.w * sWp[(k4 * 4 + 3) * 4 + ct];
            }
        }
        __syncthreads();
    }
    if (tid < 256)
        out[((size_t)(m0 + rt) * 256 + t) * 256 + n0 + ct] = acc + bp[n0 + ct];
}

// ---------------------------------------------------------------------------
// Persistent recurrence kernel: 128 CTAs x 512 threads, 3 grid barriers/step.
// ---------------------------------------------------------------------------
__global__ __launch_bounds__(512) void recurrence_kernel(
    const float* __restrict__ Wh0s, const float* __restrict__ Wt0s,
    const float* __restrict__ Whh,  const float* __restrict__ Wth,
    const float* __restrict__ bhh,  const float* __restrict__ bth,
    const float* __restrict__ Wp,   const float* __restrict__ bp,
    float* __restrict__ out)
{
    __shared__ float smp[8192];       // 32 KB pool

    int p = 0;
    for (int t = 0; t < Tc; t++) {
        // layer 0 (input-dependent adds)
        phase_step(g_s[p], g_s[p ^ 1], Wh0s, Wt0s,
                   g_xh + (size_t)t * Bc * Rc, g_xt + (size_t)t * Bc * Rc, 1,
                   smp);
        p ^= 1; gbar();
        // layer 1
        phase_step(g_s[p], g_s[p ^ 1], Whh, Wth, bhh, bth, 0, smp);
        p ^= 1; gbar();
        // layer 2
        phase_step(g_s[p], g_s[p ^ 1], Whh + 1024 * 1024, Wth + 1024 * 1024,
                   bhh + 1024, bth + 1024, 0, smp);
        p ^= 1; gbar();
        // projection of S_t (reads only g_s[p]; safe until phase 1 of t+1)
        proj_step(g_s[p], Wp, bp, out, t, smp);
        __syncthreads();   // smem handoff back to phase 0 staging
    }
}

// ---------------------------------------------------------------------------
// Host launcher (graph-capturable: 4 kernel launches total)
// ---------------------------------------------------------------------------
extern "C" void kernel_launch(void* const* d_in, const int* in_sizes, int n_in,
                              void* d_out, int out_size) {
    const int*   ids  = (const int*)  d_in[0];
    const float* emb  = (const float*)d_in[1];
    const float* Wh0x = (const float*)d_in[2];
    const float* Wh0s = (const float*)d_in[3];
    const float* bh0  = (const float*)d_in[4];
    const float* Wt0x = (const float*)d_in[5];
    const float* Wt0s = (const float*)d_in[6];
    const float* bt0  = (const float*)d_in[7];
    const float* Whh  = (const float*)d_in[8];    // [2,1024,1024]
    const float* bhh  = (const float*)d_in[9];    // [2,1024]
    const float* Wth  = (const float*)d_in[10];
    const float* bth  = (const float*)d_in[11];
    const float* Wp   = (const float*)d_in[12];   // [1024,256]
    const float* bp   = (const float*)d_in[13];
    float* out = (float*)d_out;

    zero_kernel  <<<128, 256>>>();
    gather_kernel<<<8192, 256>>>(ids, emb);
    prologue_kernel<<<dim3(64, 512), 256>>>(Wh0x, Wt0x, bh0, bt0);
    recurrence_kernel<<<128, 512>>>(Wh0s, Wt0s, Whh, Wth, bhh, bth, Wp, bp, out);
}

// round 14
// speedup vs baseline: 1.6661x; 1.0455x over previous
#include <cuda_runtime.h>
#include <math.h>

// Problem constants
static const int Bc  = 128;    // batch
static const int Tc  = 256;    // time steps
static const int Rc  = 1024;   // recurrent width

// ---------------------------------------------------------------------------
// Device scratch (no allocations allowed -> __device__ globals)
// ---------------------------------------------------------------------------
__device__ float g_x [32768 * 256];      // gathered embeddings, row = t*B + b
__device__ float g_xh[33554432];         // xh[t*B+b][r]  (x@Wh0x + bh0)
__device__ float g_xt[33554432];         // xt[t*B+b][r]  (x@Wt0x + bt0)
__device__ float g_s [2][128 * 1024];    // ping-pong state, row-major [b][r]
__device__ unsigned g_cnt = 0;           // grid barrier arrival counter
__device__ unsigned g_gen = 0;           // grid barrier generation

// 4-wide multiply-accumulate (function, NOT a macro: a macro parameter named
// `w` would capture the `.w` member token and break expansion).
static __device__ __forceinline__ void acc4(float& acc, const float4& a,
                                            const float4& b) {
    acc += a.x * b.x;
    acc += a.y * b.y;
    acc += a.z * b.z;
    acc += a.w * b.w;
}

// ---- packed fp32x2 helpers (FFMA2 path; ptxas only emits via PTX) ----------
static __device__ __forceinline__ void fma2(unsigned long long& d,
                                            unsigned long long a,
                                            unsigned long long b) {
    asm("fma.rn.f32x2 %0, %1, %2, %0;" : "+l"(d) : "l"(a), "l"(b));
}
static __device__ __forceinline__ void upk2(float& lo, float& hi,
                                            unsigned long long v) {
    asm("mov.b64 {%0, %1}, %2;" : "=f"(lo), "=f"(hi) : "l"(v));
}

// Software grid barrier for a co-resident 128-CTA persistent kernel.
static __device__ __forceinline__ void gbar() {
    __threadfence();
    __syncthreads();
    if (threadIdx.x == 0) {
        unsigned g = *((volatile unsigned*)&g_gen);
        if (atomicAdd(&g_cnt, 1) == gridDim.x - 1) {
            g_cnt = 0;
            __threadfence();
            atomicAdd(&g_gen, 1);
        } else {
            while (*((volatile unsigned*)&g_gen) == g) { }
        }
    }
    __syncthreads();
    __threadfence();
}

// ---------------------------------------------------------------------------
// Zero the initial state
// ---------------------------------------------------------------------------
__global__ void zero_kernel() {
    int i = blockIdx.x * 256 + threadIdx.x;          // 32768 float4
    ((float4*)g_s[0])[i] = make_float4(0.f, 0.f, 0.f, 0.f);
}

// ---------------------------------------------------------------------------
// Embedding gather: g_x[t*B+b][0:256] = emb[ids[b*T+t]][0:256]
// ---------------------------------------------------------------------------
__global__ void gather_kernel(const int* __restrict__ ids,
                              const float* __restrict__ emb) {
    int idx = blockIdx.x * 256 + threadIdx.x;        // 32768 rows * 64 f4
    int row = idx >> 6;
    int c   = (idx & 63) << 2;
    int t = row >> 7;            // B = 128
    int b = row & 127;
    int id = ids[b * Tc + t];
    *(float4*)&g_x[(size_t)row * 256 + c] =
        *(const float4*)&emb[(size_t)id * 256 + c];
}

// ---------------------------------------------------------------------------
// Prologue dual GEMM: xh = x@Whx + bh ; xt = x@Wtx + bt  (unchanged, works)
// ---------------------------------------------------------------------------
__global__ __launch_bounds__(256) void prologue_kernel(
    const float* __restrict__ Whx, const float* __restrict__ Wtx,
    const float* __restrict__ bh,  const float* __restrict__ bt) {
    __shared__ float sA [2][64 * 36];
    __shared__ float sWh[2][16 * 36];
    __shared__ float sWt[2][16 * 36];

    const int tid = threadIdx.x;
    const int tx  = tid & 7;
    const int ty  = tid >> 3;
    const int n0  = blockIdx.x * 16;
    const int m0  = blockIdx.y * 64;
    const int LDA = 256, LDW = 1024;

    const int sm  = tid >> 3;
    const int sk4 = (tid & 7) * 4;
    const int wn  = tid & 15;
    const int wk  = tid >> 4;

    float aH[2][2] = {{0.f,0.f},{0.f,0.f}};
    float aT[2][2] = {{0.f,0.f},{0.f,0.f}};

    #pragma unroll
    for (int r = 0; r < 2; r++) {
        int m = sm + r * 32;
        *(float4*)&sA[0][m * 36 + sk4] =
            *(const float4*)&g_x[(size_t)(m0 + m) * LDA + sk4];
    }
    #pragma unroll
    for (int r = 0; r < 2; r++) {
        int kk = wk + r * 16;
        sWh[0][wn * 36 + kk] = Whx[(size_t)kk * LDW + n0 + wn];
        sWt[0][wn * 36 + kk] = Wtx[(size_t)kk * LDW + n0 + wn];
    }
    __syncthreads();

    const int NS = 256 / 32;
    for (int st = 0; st < NS; st++) {
        const int cur = st & 1;
        float4 pA0, pA1; float pWh0, pWh1, pWt0, pWt1;
        if (st + 1 < NS) {
            int k0 = (st + 1) * 32;
            pA0 = *(const float4*)&g_x[(size_t)(m0 + sm     ) * LDA + k0 + sk4];
            pA1 = *(const float4*)&g_x[(size_t)(m0 + sm + 32) * LDA + k0 + sk4];
            pWh0 = Whx[(size_t)(k0 + wk     ) * LDW + n0 + wn];
            pWh1 = Whx[(size_t)(k0 + wk + 16) * LDW + n0 + wn];
            pWt0 = Wtx[(size_t)(k0 + wk     ) * LDW + n0 + wn];
            pWt1 = Wtx[(size_t)(k0 + wk + 16) * LDW + n0 + wn];
        }
        #pragma unroll
        for (int k4 = 0; k4 < 8; k4++) {
            float4 a0 = *(const float4*)&sA [cur][ ty       * 36 + k4 * 4];
            float4 a1 = *(const float4*)&sA [cur][(ty + 32) * 36 + k4 * 4];
            float4 h0 = *(const float4*)&sWh[cur][ tx       * 36 + k4 * 4];
            float4 h1 = *(const float4*)&sWh[cur][(tx + 8 ) * 36 + k4 * 4];
            float4 q0 = *(const float4*)&sWt[cur][ tx       * 36 + k4 * 4];
            float4 q1 = *(const float4*)&sWt[cur][(tx + 8 ) * 36 + k4 * 4];
            acc4(aH[0][0], a0, h0); acc4(aH[0][1], a0, h1);
            acc4(aH[1][0], a1, h0); acc4(aH[1][1], a1, h1);
            acc4(aT[0][0], a0, q0); acc4(aT[0][1], a0, q1);
            acc4(aT[1][0], a1, q0); acc4(aT[1][1], a1, q1);
        }
        if (st + 1 < NS) {
            int nb = cur ^ 1;
            *(float4*)&sA[nb][ sm       * 36 + sk4] = pA0;
            *(float4*)&sA[nb][(sm + 32) * 36 + sk4] = pA1;
            sWh[nb][wn * 36 + wk     ] = pWh0;
            sWh[nb][wn * 36 + wk + 16] = pWh1;
            sWt[nb][wn * 36 + wk     ] = pWt0;
            sWt[nb][wn * 36 + wk + 16] = pWt1;
        }
        __syncthreads();
    }

    #pragma unroll
    for (int r = 0; r < 2; r++)
        #pragma unroll
        for (int c = 0; c < 2; c++) {
            int m = m0 + ty + r * 32;
            int n = n0 + tx + c * 8;
            g_xh[(size_t)m * 1024 + n] = aH[r][c] + bh[n];
            g_xt[(size_t)m * 1024 + n] = aT[r][c] + bt[n];
        }
}

// ---------------------------------------------------------------------------
// One highway phase, K-packed FFMA2 version (512 threads, 4-way split-K):
//   h = tanh(addH + s@Wh);  g = sigmoid(addT + s@Wt);  s' = (h - s)*g + s
// Grid 128 CTAs: m-tile = bid>>5 (32 rows), n-tile = bid&31 (32 n-cols).
// kp = tid>>7 (split-K quarter, K=256 each, KC=16 -> 16 stages).
// Worker u = tid&127: mg = u>>5 (SAME for a whole warp -> A reads are
// full-warp broadcasts), lane = u&31 -> output col n0+lane.
// Accumulators: aH[8], aT[8] as f32x2 {even-k partial, odd-k partial};
// FFMA2 operands: A pair {a_k0,a_k1} contiguous in smem (no movs, no dup);
// W staged as float4 {wh_k0, wh_k1, wt_k0, wt_k1} per (k-pair, n) -> one
// lane-contiguous LDS.128 serves 2 k for BOTH gates.
// Per k4 per warp: 8 A-LDS(broadcast,1wf) + 2 W-LDS(4wf) + 32 FFMA2.
// Smem pool (floats): staging kp*1536 (sA 32x16=512 | sW 256 float4=1024);
// aliased post-sync by red[kp][gate][32][32] = 8192 f. Pool = 32 KB.
// ---------------------------------------------------------------------------
static __device__ void phase_step(
    const float* __restrict__ A, float* __restrict__ dst,
    const float* __restrict__ Wh, const float* __restrict__ Wt,
    const float* __restrict__ addH, const float* __restrict__ addT, int l0,
    float* smp)
{
    const int tid  = threadIdx.x;
    const int kp   = tid >> 7;
    const int u    = tid & 127;
    const int mg   = u >> 5;           // 0..3, uniform per warp
    const int lane = u & 31;           // output col
    const int m0   = (blockIdx.x >> 5) * 32;
    const int n0   = (blockIdx.x & 31) * 32;

    float*  sA = smp + kp * 1536;                  // [32 rows][16 k]
    float4* sW = (float4*)(smp + kp * 1536 + 512); // [8 kpair][32 n]

    // staging maps
    const int ar  = u >> 2;            // A row 0..31
    const int akc = (u & 3) * 4;       // A k-chunk
    const int wk2 = u >> 4;            // W k-pair 0..7
    const int wnc = (u & 15) * 2;      // W n-chunk (2 cols)
    const int gk0 = kp * 256;

    unsigned long long aH[8], aT[8];
    #pragma unroll
    for (int r = 0; r < 8; r++) { aH[r] = 0ull; aT[r] = 0ull; }

    // prefetch stage 0
    float4 rA = __ldcg((const float4*)&A[(size_t)(m0 + ar) * 1024 + gk0 + akc]);
    float2 h0 = *(const float2*)&Wh[(size_t)(gk0 + wk2 * 2    ) * 1024 + n0 + wnc];
    float2 h1 = *(const float2*)&Wh[(size_t)(gk0 + wk2 * 2 + 1) * 1024 + n0 + wnc];
    float2 q0 = *(const float2*)&Wt[(size_t)(gk0 + wk2 * 2    ) * 1024 + n0 + wnc];
    float2 q1 = *(const float2*)&Wt[(size_t)(gk0 + wk2 * 2 + 1) * 1024 + n0 + wnc];

    for (int st = 0; st < 16; st++) {
        __syncthreads();               // previous-stage consumers done
        *(float4*)&sA[ar * 16 + akc] = rA;
        sW[wk2 * 32 + wnc    ] = make_float4(h0.x, h1.x, q0.x, q1.x);
        sW[wk2 * 32 + wnc + 1] = make_float4(h0.y, h1.y, q0.y, q1.y);
        __syncthreads();               // staging visible
        if (st < 15) {                 // prefetch next stage (hidden by compute)
            int k0 = gk0 + (st + 1) * 16;
            rA = __ldcg((const float4*)&A[(size_t)(m0 + ar) * 1024 + k0 + akc]);
            h0 = *(const float2*)&Wh[(size_t)(k0 + wk2 * 2    ) * 1024 + n0 + wnc];
            h1 = *(const float2*)&Wh[(size_t)(k0 + wk2 * 2 + 1) * 1024 + n0 + wnc];
            q0 = *(const float2*)&Wt[(size_t)(k0 + wk2 * 2    ) * 1024 + n0 + wnc];
            q1 = *(const float2*)&Wt[(size_t)(k0 + wk2 * 2 + 1) * 1024 + n0 + wnc];
        }
        #pragma unroll
        for (int k4 = 0; k4 < 4; k4++) {
            // W pairs for k = 4*k4..4*k4+3: {wh_lo,wh_hi},{wt_lo,wt_hi}
            ulonglong2 w0 = *(const ulonglong2*)&sW[(k4 * 2    ) * 32 + lane];
            ulonglong2 w1 = *(const ulonglong2*)&sW[(k4 * 2 + 1) * 32 + lane];
            #pragma unroll
            for (int r = 0; r < 8; r++) {
                ulonglong2 av =
                    *(const ulonglong2*)&sA[(mg * 8 + r) * 16 + k4 * 4];
                fma2(aH[r], av.x, w0.x); fma2(aT[r], av.x, w0.y);
                fma2(aH[r], av.y, w1.x); fma2(aT[r], av.y, w1.y);
            }
        }
    }
    __syncthreads();                   // all compute done before aliasing smem

    // split-K reduction staging: red[kp][gate][row32][col32]
    #pragma unroll
    for (int r = 0; r < 8; r++) {
        int row = mg * 8 + r;
        float lo, hi;
        upk2(lo, hi, aH[r]);
        smp[kp * 2048 +        row * 32 + lane] = lo + hi;
        upk2(lo, hi, aT[r]);
        smp[kp * 2048 + 1024 + row * 32 + lane] = lo + hi;
    }
    __syncthreads();

    // epilogue: 1024 state outputs, 2 per thread
    #pragma unroll
    for (int i = 0; i < 2; i++) {
        int p2  = tid * 2 + i;
        int row = p2 >> 5, col = p2 & 31;
        float H = smp[       row * 32 + col] + smp[2048 +        row * 32 + col]
                + smp[4096 + row * 32 + col] + smp[6144 +        row * 32 + col];
        float T = smp[1024 + row * 32 + col] + smp[3072 +        row * 32 + col]
                + smp[5120 + row * 32 + col] + smp[7168 +        row * 32 + col];
        int m = m0 + row, n = n0 + col;
        size_t off = (size_t)m * 1024 + n;
        float addh = l0 ? addH[off] : addH[n];
        float addt = l0 ? addT[off] : addT[n];
        float so   = __ldcg(&A[off]);
        float hh   = tanhf(addh + H);
        float gg   = 1.f / (1.f + expf(-(addt + T)));
        dst[off]   = (hh - so) * gg + so;
    }
}

// ---------------------------------------------------------------------------
// Projection (512-thread, validated): out[(b*T+t)*256+n] = S@Wp + bp
// This CTA: rows m0..m0+63 (m0 = (bid>>6)*64), cols n0..n0+3 (n0=(bid&63)*4).
// All 512 threads stage; threads 0..255 compute.
// ---------------------------------------------------------------------------
static __device__ void proj_step(const float* __restrict__ A,
                                 const float* __restrict__ Wp,
                                 const float* __restrict__ bp,
                                 float* __restrict__ out, int t,
                                 float* smp)
{
    float* sAf = smp;              // 64*68 = 4352 floats
    float* sWp = smp + 4352;       // 256 floats
    const int tid = threadIdx.x;
    const int m0  = (blockIdx.x >> 6) * 64;
    const int n0  = (blockIdx.x & 63) * 4;
    const int rt  = tid & 63;          // output row within tile
    const int ct  = (tid >> 6) & 3;    // output col 0..3
    const int sr  = tid >> 3;          // staging row 0..63
    const int sc  = (tid & 7) * 8;     // staging k-offset (2 f4 per thread)
    float acc = 0.f;

    for (int k0 = 0; k0 < 1024; k0 += 64) {
        *(float4*)&sAf[sr * 68 + sc] =
            __ldcg((const float4*)&A[(size_t)(m0 + sr) * 1024 + k0 + sc]);
        *(float4*)&sAf[sr * 68 + sc + 4] =
            __ldcg((const float4*)&A[(size_t)(m0 + sr) * 1024 + k0 + sc + 4]);
        if (tid < 64)
            *(float4*)&sWp[tid * 4] =
                *(const float4*)&Wp[(size_t)(k0 + tid) * 256 + n0];
        __syncthreads();
        if (tid < 256) {
            #pragma unroll
            for (int k4 = 0; k4 < 16; k4++) {
                float4 a = *(const float4*)&sAf[rt * 68 + k4 * 4];
                acc += a.x * sWp[(k4 * 4 + 0) * 4 + ct];
                acc += a.y * sWp[(k4 * 4 + 1) * 4 + ct];
                acc += a.z * sWp[(k4 * 4 + 2) * 4 + ct];
                acc += a.w * sWp[(k4 * 4 + 3) * 4 + ct];
            }
        }
        __syncthreads();
    }
    if (tid < 256)
        out[((size_t)(m0 + rt) * 256 + t) * 256 + n0 + ct] = acc + bp[n0 + ct];
}

// ---------------------------------------------------------------------------
// Persistent recurrence kernel: 128 CTAs x 512 threads, 3 grid barriers/step.
// ---------------------------------------------------------------------------
__global__ __launch_bounds__(512) void recurrence_kernel(
    const float* __restrict__ Wh0s, const float* __restrict__ Wt0s,
    const float* __restrict__ Whh,  const float* __restrict__ Wth,
    const float* __restrict__ bhh,  const float* __restrict__ bth,
    const float* __restrict__ Wp,   const float* __restrict__ bp,
    float* __restrict__ out)
{
    __shared__ float smp[8192];       // 32 KB pool

    int p = 0;
    for (int t = 0; t < Tc; t++) {
        // layer 0 (input-dependent adds)
        phase_step(g_s[p], g_s[p ^ 1], Wh0s, Wt0s,
                   g_xh + (size_t)t * Bc * Rc, g_xt + (size_t)t * Bc * Rc, 1,
                   smp);
        p ^= 1; gbar();
        // layer 1
        phase_step(g_s[p], g_s[p ^ 1], Whh, Wth, bhh, bth, 0, smp);
        p ^= 1; gbar();
        // layer 2
        phase_step(g_s[p], g_s[p ^ 1], Whh + 1024 * 1024, Wth + 1024 * 1024,
                   bhh + 1024, bth + 1024, 0, smp);
        p ^= 1; gbar();
        // projection of S_t (reads only g_s[p]; safe until phase 1 of t+1)
        proj_step(g_s[p], Wp, bp, out, t, smp);
        __syncthreads();   // smem handoff back to phase 0 staging
    }
}

// ---------------------------------------------------------------------------
// Host launcher (graph-capturable: 4 kernel launches total)
// ---------------------------------------------------------------------------
extern "C" void kernel_launch(void* const* d_in, const int* in_sizes, int n_in,
                              void* d_out, int out_size) {
    const int*   ids  = (const int*)  d_in[0];
    const float* emb  = (const float*)d_in[1];
    const float* Wh0x = (const float*)d_in[2];
    const float* Wh0s = (const float*)d_in[3];
    const float* bh0  = (const float*)d_in[4];
    const float* Wt0x = (const float*)d_in[5];
    const float* Wt0s = (const float*)d_in[6];
    const float* bt0  = (const float*)d_in[7];
    const float* Whh  = (const float*)d_in[8];    // [2,1024,1024]
    const float* bhh  = (const float*)d_in[9];    // [2,1024]
    const float* Wth  = (const float*)d_in[10];
    const float* bth  = (const float*)d_in[11];
    const float* Wp   = (const float*)d_in[12];   // [1024,256]
    const float* bp   = (const float*)d_in[13];
    float* out = (float*)d_out;

    zero_kernel  <<<128, 256>>>();
    gather_kernel<<<8192, 256>>>(ids, emb);
    prologue_kernel<<<dim3(64, 512), 256>>>(Wh0x, Wt0x, bh0, bt0);
    recurrence_kernel<<<128, 512>>>(Wh0s, Wt0s, Whh, Wth, bhh, bth, Wp, bp, out);
}

// round 17
// speedup vs baseline: 2.1632x; 1.2984x over previous
#include <cuda_runtime.h>
#include <cuda_bf16.h>
#include <cstdint>
#include <math.h>

// Problem constants
static const int Bc  = 128;    // batch
static const int Tc  = 256;    // time steps
static const int Rc  = 1024;   // recurrent width

// ---------------------------------------------------------------------------
// Device scratch (no allocations allowed -> __device__ globals)
// ---------------------------------------------------------------------------
__device__ float g_x [32768 * 256];      // gathered embeddings, row = t*B + b
__device__ float g_xh[33554432];         // xh[t*B+b][r]  (x@Wh0x + bh0)
__device__ float g_xt[33554432];         // xt[t*B+b][r]  (x@Wt0x + bt0)
__device__ float g_s [2][128 * 1024];    // ping-pong fp32 state [b][r]
__device__ __nv_bfloat16 g_sbh[2][128 * 1024];  // state hi (bf16), ping-pong
__device__ __nv_bfloat16 g_sbl[2][128 * 1024];  // state lo (bf16), ping-pong
// Pre-converted weights, TRANSPOSED [n][k], bf16 hi/lo.
// matrix index: 0=Wh0s 1=Wt0s 2=Whh0 3=Wth0 4=Whh1 5=Wth1
__device__ __nv_bfloat16 g_Wbh[6 * 1024 * 1024];
__device__ __nv_bfloat16 g_Wbl[6 * 1024 * 1024];
__device__ unsigned g_cnt = 0;           // grid barrier arrival counter
__device__ unsigned g_gen = 0;           // grid barrier generation

// 4-wide multiply-accumulate (function, NOT a macro: a macro parameter named
// `w` would capture the `.w` member token and break expansion).
static __device__ __forceinline__ void acc4(float& acc, const float4& a,
                                            const float4& b) {
    acc += a.x * b.x;
    acc += a.y * b.y;
    acc += a.z * b.z;
    acc += a.w * b.w;
}

// bf16 HMMA m16n8k16 (classic mma.sync -- supported on plain sm_103 target;
// tcgen05 is NOT, the harness compiles for sm_103 without the 'a' suffix).
static __device__ __forceinline__ void mma16816(float* d,
    uint32_t a0, uint32_t a1, uint32_t a2, uint32_t a3,
    uint32_t b0, uint32_t b1) {
    asm volatile(
        "mma.sync.aligned.m16n8k16.row.col.f32.bf16.bf16.f32 "
        "{%0,%1,%2,%3}, {%4,%5,%6,%7}, {%8,%9}, {%0,%1,%2,%3};"
        : "+f"(d[0]), "+f"(d[1]), "+f"(d[2]), "+f"(d[3])
        : "r"(a0), "r"(a1), "r"(a2), "r"(a3), "r"(b0), "r"(b1));
}

// Software grid barrier for a co-resident 128-CTA persistent kernel.
static __device__ __forceinline__ void gbar() {
    __threadfence();
    __syncthreads();
    if (threadIdx.x == 0) {
        unsigned g = *((volatile unsigned*)&g_gen);
        if (atomicAdd(&g_cnt, 1) == gridDim.x - 1) {
            g_cnt = 0;
            __threadfence();
            atomicAdd(&g_gen, 1);
        } else {
            while (*((volatile unsigned*)&g_gen) == g) { }
        }
    }
    __syncthreads();
    __threadfence();
}

// ---------------------------------------------------------------------------
// Zero the initial state (fp32 + bf16 hi/lo)
// ---------------------------------------------------------------------------
__global__ void zero_kernel() {
    int i = blockIdx.x * 256 + threadIdx.x;          // 32768 float4
    ((float4*)g_s[0])[i] = make_float4(0.f, 0.f, 0.f, 0.f);
    if (i < 16384) {
        ((float4*)g_sbh[0])[i] = make_float4(0.f, 0.f, 0.f, 0.f);
        ((float4*)g_sbl[0])[i] = make_float4(0.f, 0.f, 0.f, 0.f);
    }
}

// ---------------------------------------------------------------------------
// Embedding gather: g_x[t*B+b][0:256] = emb[ids[b*T+t]][0:256]
// ---------------------------------------------------------------------------
__global__ void gather_kernel(const int* __restrict__ ids,
                              const float* __restrict__ emb) {
    int idx = blockIdx.x * 256 + threadIdx.x;        // 32768 rows * 64 f4
    int row = idx >> 6;
    int c   = (idx & 63) << 2;
    int t = row >> 7;            // B = 128
    int b = row & 127;
    int id = ids[b * Tc + t];
    *(float4*)&g_x[(size_t)row * 256 + c] =
        *(const float4*)&emb[(size_t)id * 256 + c];
}

// ---------------------------------------------------------------------------
// Weight conversion: fp32 W[k][n] -> transposed bf16 hi/lo [n][k].
// grid (32 n-tiles, 32 k-tiles, 6 matrices), block (32, 8). Tiled transpose.
// ---------------------------------------------------------------------------
__global__ void convert_kernel(const float* __restrict__ Wh0s,
                               const float* __restrict__ Wt0s,
                               const float* __restrict__ Whh,
                               const float* __restrict__ Wth) {
    __shared__ float tile[32][33];
    int mat = blockIdx.z;
    const float* src =
        mat == 0 ? Wh0s : mat == 1 ? Wt0s :
        mat == 2 ? Whh  : mat == 3 ? Wth  :
        mat == 4 ? (Whh + 1048576) : (Wth + 1048576);
    int tx = threadIdx.x, ty = threadIdx.y;
    int n  = blockIdx.x * 32 + tx;
    int kb = blockIdx.y * 32;
    #pragma unroll
    for (int r = 0; r < 4; r++)
        tile[ty + r * 8][tx] = src[(size_t)(kb + ty + r * 8) * 1024 + n];
    __syncthreads();
    int k  = kb + tx;
    int nb = blockIdx.x * 32;
    #pragma unroll
    for (int r = 0; r < 4; r++) {
        float v = tile[tx][ty + r * 8];              // src[k][nb+ty+r*8]
        int nn = nb + ty + r * 8;
        size_t di = (size_t)mat * 1048576 + (size_t)nn * 1024 + k;
        __nv_bfloat16 h = __float2bfloat16(v);
        g_Wbh[di] = h;
        g_Wbl[di] = __float2bfloat16(v - __bfloat162float(h));
    }
}

// ---------------------------------------------------------------------------
// Prologue dual GEMM: xh = x@Whx + bh ; xt = x@Wtx + bt  (unchanged, works)
// ---------------------------------------------------------------------------
__global__ __launch_bounds__(256) void prologue_kernel(
    const float* __restrict__ Whx, const float* __restrict__ Wtx,
    const float* __restrict__ bh,  const float* __restrict__ bt) {
    __shared__ float sA [2][64 * 36];
    __shared__ float sWh[2][16 * 36];
    __shared__ float sWt[2][16 * 36];

    const int tid = threadIdx.x;
    const int tx  = tid & 7;
    const int ty  = tid >> 3;
    const int n0  = blockIdx.x * 16;
    const int m0  = blockIdx.y * 64;
    const int LDA = 256, LDW = 1024;

    const int sm  = tid >> 3;
    const int sk4 = (tid & 7) * 4;
    const int wn  = tid & 15;
    const int wk  = tid >> 4;

    float aH[2][2] = {{0.f,0.f},{0.f,0.f}};
    float aT[2][2] = {{0.f,0.f},{0.f,0.f}};

    #pragma unroll
    for (int r = 0; r < 2; r++) {
        int m = sm + r * 32;
        *(float4*)&sA[0][m * 36 + sk4] =
            *(const float4*)&g_x[(size_t)(m0 + m) * LDA + sk4];
    }
    #pragma unroll
    for (int r = 0; r < 2; r++) {
        int kk = wk + r * 16;
        sWh[0][wn * 36 + kk] = Whx[(size_t)kk * LDW + n0 + wn];
        sWt[0][wn * 36 + kk] = Wtx[(size_t)kk * LDW + n0 + wn];
    }
    __syncthreads();

    const int NS = 256 / 32;
    for (int st = 0; st < NS; st++) {
        const int cur = st & 1;
        float4 pA0, pA1; float pWh0, pWh1, pWt0, pWt1;
        if (st + 1 < NS) {
            int k0 = (st + 1) * 32;
            pA0 = *(const float4*)&g_x[(size_t)(m0 + sm     ) * LDA + k0 + sk4];
            pA1 = *(const float4*)&g_x[(size_t)(m0 + sm + 32) * LDA + k0 + sk4];
            pWh0 = Whx[(size_t)(k0 + wk     ) * LDW + n0 + wn];
            pWh1 = Whx[(size_t)(k0 + wk + 16) * LDW + n0 + wn];
            pWt0 = Wtx[(size_t)(k0 + wk     ) * LDW + n0 + wn];
            pWt1 = Wtx[(size_t)(k0 + wk + 16) * LDW + n0 + wn];
        }
        #pragma unroll
        for (int k4 = 0; k4 < 8; k4++) {
            float4 a0 = *(const float4*)&sA [cur][ ty       * 36 + k4 * 4];
            float4 a1 = *(const float4*)&sA [cur][(ty + 32) * 36 + k4 * 4];
            float4 h0 = *(const float4*)&sWh[cur][ tx       * 36 + k4 * 4];
            float4 h1 = *(const float4*)&sWh[cur][(tx + 8 ) * 36 + k4 * 4];
            float4 q0 = *(const float4*)&sWt[cur][ tx       * 36 + k4 * 4];
            float4 q1 = *(const float4*)&sWt[cur][(tx + 8 ) * 36 + k4 * 4];
            acc4(aH[0][0], a0, h0); acc4(aH[0][1], a0, h1);
            acc4(aH[1][0], a1, h0); acc4(aH[1][1], a1, h1);
            acc4(aT[0][0], a0, q0); acc4(aT[0][1], a0, q1);
            acc4(aT[1][0], a1, q0); acc4(aT[1][1], a1, q1);
        }
        if (st + 1 < NS) {
            int nb = cur ^ 1;
            *(float4*)&sA[nb][ sm       * 36 + sk4] = pA0;
            *(float4*)&sA[nb][(sm + 32) * 36 + sk4] = pA1;
            sWh[nb][wn * 36 + wk     ] = pWh0;
            sWh[nb][wn * 36 + wk + 16] = pWh1;
            sWt[nb][wn * 36 + wk     ] = pWt0;
            sWt[nb][wn * 36 + wk + 16] = pWt1;
        }
        __syncthreads();
    }

    #pragma unroll
    for (int r = 0; r < 2; r++)
        #pragma unroll
        for (int c = 0; c < 2; c++) {
            int m = m0 + ty + r * 32;
            int n = n0 + tx + c * 8;
            g_xh[(size_t)m * 1024 + n] = aH[r][c] + bh[n];
            g_xt[(size_t)m * 1024 + n] = aT[r][c] + bt[n];
        }
}

// ---------------------------------------------------------------------------
// HMMA highway phase (512 threads). CTA tile: M=64 rows x 16 n-cols x 2 gates.
// grid: m-tile = bid>>6 (2 tiles of 64), n-tile = bid&63 (16 cols per gate).
// Warps: wid>>2 = kq (k-quarter, 256 k), wid&3 = mf (m16 frag).
// Each warp: its m16 frag x ALL 32 outcols (4 n8 frags) over its k-quarter.
// Split-bf16: D = Ah*Bh + Ah*Bl + Al*Bh (fp32 acc in registers).
// smem stage (floats): Ahi[64][36] @0 | Alo @2304 | Bhi[32][36] @4608 |
// Blo @5760 (stride 72 bf16 = 36 words -> banks 4r+kw, conflict-free).
// After compute, pool aliased by red[kq][64][32] floats (8192 f = 32 KB).
// B tile rows: 0..15 = H gate cols, 16..31 = T gate cols.
// ---------------------------------------------------------------------------
static __device__ void phase_hmma(
    const float* __restrict__ Sold, float* __restrict__ Snew,
    const __nv_bfloat16* __restrict__ Abh, const __nv_bfloat16* __restrict__ Abl,
    __nv_bfloat16* __restrict__ Obh, __nv_bfloat16* __restrict__ Obl,
    int mh, int mt,
    const float* __restrict__ addH, const float* __restrict__ addT, int l0,
    float* smp)
{
    const int tid  = threadIdx.x;
    const int lane = tid & 31;
    const int wid  = tid >> 5;
    const int kq   = wid >> 2;         // k-quarter 0..3
    const int mf   = wid & 3;          // m16 fragment 0..3
    const int rr   = lane >> 2;        // fragment row 0..7
    const int lq   = lane & 3;         // fragment k-word 0..3
    const int m0   = (blockIdx.x >> 6) * 64;
    const int n0   = (blockIdx.x & 63) * 16;

    // staging maps
    const int arow = tid >> 3;          // 0..63
    const int ac   = tid & 7;           // 8-bf16 chunk
    const int bu   = tid & 255;
    const int brow = bu >> 3;           // 0..31 (B tile row)
    const int bc   = bu & 7;
    const int bmat = (brow < 16) ? mh : mt;
    const int bcol = n0 + (brow & 15);
    const __nv_bfloat16* wsrc =
        ((tid < 256) ? g_Wbh : g_Wbl)
        + (size_t)bmat * 1048576 + (size_t)bcol * 1024;
    const int aDstF = arow * 36 + ac * 4;             // float offset (uint4 ok)
    const int bDstF = ((tid < 256) ? 4608 : 5760) + brow * 36 + bc * 4;

    float acc[4][4];
    #pragma unroll
    for (int nf = 0; nf < 4; nf++)
        #pragma unroll
        for (int i = 0; i < 4; i++) acc[nf][i] = 0.f;

    // prefetch stage 0
    uint4 pa0 = __ldcg((const uint4*)(Abh + (size_t)(m0 + arow) * 1024 + ac * 8));
    uint4 pa1 = __ldcg((const uint4*)(Abl + (size_t)(m0 + arow) * 1024 + ac * 8));
    uint4 pb  = *(const uint4*)(wsrc + bc * 8);

    for (int st = 0; st < 16; st++) {
        __syncthreads();               // previous-stage consumers done
        *(uint4*)(smp + aDstF)        = pa0;
        *(uint4*)(smp + 2304 + aDstF) = pa1;
        *(uint4*)(smp + bDstF)        = pb;
        __syncthreads();               // staging visible
        if (st < 15) {
            int k0 = (st + 1) * 64;
            pa0 = __ldcg((const uint4*)(Abh + (size_t)(m0 + arow) * 1024 + k0 + ac * 8));
            pa1 = __ldcg((const uint4*)(Abl + (size_t)(m0 + arow) * 1024 + k0 + ac * 8));
            pb  = *(const uint4*)(wsrc + k0 + bc * 8);
        }
        if ((st >> 2) == kq) {
            const uint32_t* sa = (const uint32_t*)smp;
            #pragma unroll
            for (int ks = 0; ks < 4; ks++) {
                int ab = (mf * 16 + rr) * 36 + ks * 8 + lq;
                uint32_t ah0 = sa[ab],            ah1 = sa[ab + 288];
                uint32_t ah2 = sa[ab + 4],        ah3 = sa[ab + 292];
                uint32_t al0 = sa[2304 + ab],     al1 = sa[2304 + ab + 288];
                uint32_t al2 = sa[2304 + ab + 4], al3 = sa[2304 + ab + 292];
                #pragma unroll
                for (int nf = 0; nf < 4; nf++) {
                    int bb = 4608 + (nf * 8 + rr) * 36 + ks * 8 + lq;
                    uint32_t bh0 = sa[bb],        bh1 = sa[bb + 4];
                    uint32_t bl0 = sa[bb + 1152], bl1 = sa[bb + 1156];
                    mma16816(acc[nf], ah0, ah1, ah2, ah3, bh0, bh1);
                    mma16816(acc[nf], ah0, ah1, ah2, ah3, bl0, bl1);
                    mma16816(acc[nf], al0, al1, al2, al3, bh0, bh1);
                }
            }
        }
    }
    __syncthreads();                   // all compute done before aliasing smem

    // split-K partials: red[kq][row64][col32]  (col 0..15 H, 16..31 T)
    #pragma unroll
    for (int nf = 0; nf < 4; nf++) {
        int r0 = mf * 16 + rr;
        int c0 = nf * 8 + lq * 2;
        smp[kq * 2048 +  r0      * 32 + c0    ] = acc[nf][0];
        smp[kq * 2048 +  r0      * 32 + c0 + 1] = acc[nf][1];
        smp[kq * 2048 + (r0 + 8) * 32 + c0    ] = acc[nf][2];
        smp[kq * 2048 + (r0 + 8) * 32 + c0 + 1] = acc[nf][3];
    }
    __syncthreads();

    // epilogue: 1024 state outputs, 2 per thread
    #pragma unroll
    for (int i = 0; i < 2; i++) {
        int s   = tid * 2 + i;
        int row = s >> 4, nc = s & 15;
        float H = smp[       row * 32 + nc] + smp[2048 + row * 32 + nc]
                + smp[4096 + row * 32 + nc] + smp[6144 + row * 32 + nc];
        float T = smp[       row * 32 + 16 + nc] + smp[2048 + row * 32 + 16 + nc]
                + smp[4096 + row * 32 + 16 + nc] + smp[6144 + row * 32 + 16 + nc];
        int m = m0 + row, n = n0 + nc;
        size_t off = (size_t)m * 1024 + n;
        float addh = l0 ? addH[off] : addH[n];
        float addt = l0 ? addT[off] : addT[n];
        float so   = __ldcg(&Sold[off]);
        float hh   = tanhf(addh + H);
        float gg   = 1.f / (1.f + expf(-(addt + T)));
        float sn   = (hh - so) * gg + so;
        Snew[off]  = sn;
        __nv_bfloat16 hb = __float2bfloat16(sn);
        Obh[off] = hb;
        Obl[off] = __float2bfloat16(sn - __bfloat162float(hb));
    }
}

// ---------------------------------------------------------------------------
// Projection (512-thread, validated): out[(b*T+t)*256+n] = S@Wp + bp
// ---------------------------------------------------------------------------
static __device__ void proj_step(const float* __restrict__ A,
                                 const float* __restrict__ Wp,
                                 const float* __restrict__ bp,
                                 float* __restrict__ out, int t,
                                 float* smp)
{
    float* sAf = smp;              // 64*68 = 4352 floats
    float* sWp = smp + 4352;       // 256 floats
    const int tid = threadIdx.x;
    const int m0  = (blockIdx.x >> 6) * 64;
    const int n0  = (blockIdx.x & 63) * 4;
    const int rt  = tid & 63;
    const int ct  = (tid >> 6) & 3;
    const int sr  = tid >> 3;
    const int sc  = (tid & 7) * 8;
    float acc = 0.f;

    for (int k0 = 0; k0 < 1024; k0 += 64) {
        *(float4*)&sAf[sr * 68 + sc] =
            __ldcg((const float4*)&A[(size_t)(m0 + sr) * 1024 + k0 + sc]);
        *(float4*)&sAf[sr * 68 + sc + 4] =
            __ldcg((const float4*)&A[(size_t)(m0 + sr) * 1024 + k0 + sc + 4]);
        if (tid < 64)
            *(float4*)&sWp[tid * 4] =
                *(const float4*)&Wp[(size_t)(k0 + tid) * 256 + n0];
        __syncthreads();
        if (tid < 256) {
            #pragma unroll
            for (int k4 = 0; k4 < 16; k4++) {
                float4 a = *(const float4*)&sAf[rt * 68 + k4 * 4];
                acc += a.x * sWp[(k4 * 4 + 0) * 4 + ct];
                acc += a.y * sWp[(k4 * 4 + 1) * 4 + ct];
                acc += a.z * sWp[(k4 * 4 + 2) * 4 + ct];
                acc += a.w * sWp[(k4 * 4 + 3) * 4 + ct];
            }
        }
        __syncthreads();
    }
    if (tid < 256)
        out[((size_t)(m0 + rt) * 256 + t) * 256 + n0 + ct] = acc + bp[n0 + ct];
}

// ---------------------------------------------------------------------------
// Persistent recurrence kernel: 128 CTAs x 512 threads, HMMA phases.
// ---------------------------------------------------------------------------
__global__ __launch_bounds__(512) void recurrence_kernel(
    const float* __restrict__ Wp, const float* __restrict__ bp,
    const float* __restrict__ bhh, const float* __restrict__ bth,
    float* __restrict__ out)
{
    __shared__ float smp[8192];       // 32 KB pool

    int p = 0;
    for (int t = 0; t < Tc; t++) {
        // layer 0 (input-dependent adds): matrices 0,1
        phase_hmma(g_s[p], g_s[p ^ 1], g_sbh[p], g_sbl[p],
                   g_sbh[p ^ 1], g_sbl[p ^ 1], 0, 1,
                   g_xh + (size_t)t * Bc * Rc, g_xt + (size_t)t * Bc * Rc, 1,
                   smp);
        p ^= 1; gbar();
        // layer 1: matrices 2,3
        phase_hmma(g_s[p], g_s[p ^ 1], g_sbh[p], g_sbl[p],
                   g_sbh[p ^ 1], g_sbl[p ^ 1], 2, 3,
                   bhh, bth, 0, smp);
        p ^= 1; gbar();
        // layer 2: matrices 4,5
        phase_hmma(g_s[p], g_s[p ^ 1], g_sbh[p], g_sbl[p],
                   g_sbh[p ^ 1], g_sbl[p ^ 1], 4, 5,
                   bhh + 1024, bth + 1024, 0, smp);
        p ^= 1; gbar();
        // projection of S_t (reads g_s[p] fp32; safe until phase 1 of t+1)
        proj_step(g_s[p], Wp, bp, out, t, smp);
        __syncthreads();
    }
}

// ---------------------------------------------------------------------------
// Host launcher (graph-capturable: 5 kernel launches total)
// ---------------------------------------------------------------------------
extern "C" void kernel_launch(void* const* d_in, const int* in_sizes, int n_in,
                              void* d_out, int out_size) {
    const int*   ids  = (const int*)  d_in[0];
    const float* emb  = (const float*)d_in[1];
    const float* Wh0x = (const float*)d_in[2];
    const float* Wh0s = (const float*)d_in[3];
    const float* bh0  = (const float*)d_in[4];
    const float* Wt0x = (const float*)d_in[5];
    const float* Wt0s = (const float*)d_in[6];
    const float* bt0  = (const float*)d_in[7];
    const float* Whh  = (const float*)d_in[8];    // [2,1024,1024]
    const float* bhh  = (const float*)d_in[9];    // [2,1024]
    const float* Wth  = (const float*)d_in[10];
    const float* bth  = (const float*)d_in[11];
    const float* Wp   = (const float*)d_in[12];   // [1024,256]
    const float* bp   = (const float*)d_in[13];
    float* out = (float*)d_out;

    zero_kernel   <<<128, 256>>>();
    gather_kernel <<<8192, 256>>>(ids, emb);
    convert_kernel<<<dim3(32, 32, 6), dim3(32, 8)>>>(Wh0s, Wt0s, Whh, Wth);
    prologue_kernel<<<dim3(64, 512), 256>>>(Wh0x, Wt0x, bh0, bt0);
    recurrence_kernel<<<128, 512>>>(Wp, bp, bhh, bth, out);
}